// round 15
// baseline (speedup 1.0000x reference)
#include <cuda_runtime.h>
#include <cuda_fp16.h>
#include <cstdint>
#include <cstddef>

// ---------------- problem constants ----------------
#define N_NODES 50000
#define N_EDGES 1600000
constexpr int D0 = 512, D1 = 2048, D2 = 1024, D3 = 512;
constexpr int M_HALF = 25000;

// ---------------- device scratch ----------------
__device__ int    g_cnt[N_NODES];            // zero at load; re-zeroed by scatter each call
__device__ int    g_rowptr[N_NODES + 1];
__device__ int    g_cursor[N_NODES];
__device__ int2   g_epair[N_EDGES];
__device__ __half g_xh[N_NODES * D0];
__device__ __half g_t1[N_NODES * D0];
__device__ __half g_h1[(size_t)N_NODES * D1];
__device__ __half g_s2[N_NODES * D2];
__device__ __half g_h2[N_NODES * D2];
__device__ __half g_s3[N_NODES * D3];
__device__ __half g_W0h[D0 * D1];
__device__ __half g_W1h[D1 * D2];
__device__ __half g_W2h[D2 * D3];

// ---------------- normalize + fp16 convert + degree count + W0 f2h (fused) ----------------
__global__ void normh_count_kernel(const float* __restrict__ x, __half* __restrict__ xh,
                                   const int* __restrict__ erow, int* __restrict__ cnt, int E,
                                   const float* __restrict__ W, __half* __restrict__ Wh, int nW) {
    int row = blockIdx.x, tid = threadIdx.x;
    const float4* x4 = reinterpret_cast<const float4*>(x);
    float4 v = x4[(size_t)row * (D0 / 4) + tid];
    float ss = v.x * v.x + v.y * v.y + v.z * v.z + v.w * v.w;
    #pragma unroll
    for (int o = 16; o; o >>= 1) ss += __shfl_xor_sync(0xffffffffu, ss, o);
    __shared__ float sw[4];
    __shared__ float s_inv;
    if ((tid & 31) == 0) sw[tid >> 5] = ss;
    __syncthreads();
    if (tid == 0) {
        float t = sw[0] + sw[1] + sw[2] + sw[3];
        s_inv = 1.0f / fmaxf(sqrtf(t), 1e-12f);
    }
    __syncthreads();
    float inv = s_inv;
    __half2* o2 = reinterpret_cast<__half2*>(xh) + (size_t)row * (D0 / 2) + tid * 2;
    o2[0] = __floats2half2_rn(v.x * inv, v.y * inv);
    o2[1] = __floats2half2_rn(v.z * inv, v.w * inv);
    int gstride = gridDim.x * blockDim.x;
    int g0 = blockIdx.x * blockDim.x + tid;
    for (int i = g0; i < E; i += gstride)
        atomicAdd(&cnt[erow[i]], 1);
    for (int i = g0; i < nW; i += gstride)
        Wh[i] = __float2half_rn(W[i]);
}

__global__ void scan_kernel(const int* __restrict__ cnt, int* __restrict__ rowptr,
                            int* __restrict__ cursor) {
    __shared__ int sh[1024];
    __shared__ int carry;
    int t = threadIdx.x;
    if (t == 0) { carry = 0; rowptr[0] = 0; cursor[0] = 0; }
    __syncthreads();
    for (int base = 0; base < N_NODES; base += 1024) {
        int i = base + t;
        int v = (i < N_NODES) ? cnt[i] : 0;
        sh[t] = v;
        __syncthreads();
        #pragma unroll
        for (int off = 1; off < 1024; off <<= 1) {
            int u = (t >= off) ? sh[t - off] : 0;
            __syncthreads();
            sh[t] += u;
            __syncthreads();
        }
        if (i < N_NODES) {
            int val = carry + sh[t];
            rowptr[i + 1] = val;
            if (i + 1 < N_NODES) cursor[i + 1] = val;
        }
        __syncthreads();
        if (t == 0) carry += sh[1023];
        __syncthreads();
    }
}

__global__ void scatter_kernel(const int* __restrict__ erow, const int* __restrict__ ecol,
                               const float* __restrict__ eval, int* __restrict__ cursor,
                               int2* __restrict__ epair, int* __restrict__ cnt, int E) {
    int gstride = gridDim.x * blockDim.x;
    int g0 = blockIdx.x * blockDim.x + threadIdx.x;
    for (int i = g0; i < E; i += gstride) {
        int r = erow[i];
        int p = atomicAdd(&cursor[r], 1);
        epair[p] = make_int2(ecol[i], __float_as_int(eval[i]));
    }
    for (int i = g0; i < N_NODES; i += gstride)
        cnt[i] = 0;
}

// convert W1 and W2 in one launch (side stream, overlapped with CSR build)
__global__ void f2h2_kernel(const float* __restrict__ in1, __half* __restrict__ out1, int n1,
                            const float* __restrict__ in2, __half* __restrict__ out2, int n2) {
    int gstride = gridDim.x * blockDim.x;
    int g0 = blockIdx.x * blockDim.x + threadIdx.x;
    for (int i = g0; i < n1; i += gstride) out1[i] = __float2half_rn(in1[i]);
    for (int i = g0; i < n2; i += gstride) out2[i] = __float2half_rn(in2[i]);
}

// ---------------- SPMM (fp16 src, packed edges, FFMA accum) ----------------
// DS = full row width (halves) of src AND out. blockDim covers a column slice;
// row0 = output row offset, coff8 = column offset in uint4 (8-half) units.
template <int DS, bool BIAS, bool LEAKY, typename OutT>
__global__ void spmm_h_kernel(const int* __restrict__ rowptr, const int2* __restrict__ epair,
                              const __half* __restrict__ src,
                              const float* __restrict__ bias, OutT* __restrict__ out,
                              int row0, int coff8) {
    const int row = blockIdx.x + row0;
    const int tid = threadIdx.x;
    int s = __ldg(&rowptr[row]), e = __ldg(&rowptr[row + 1]);
    float acc[8];
    #pragma unroll
    for (int j = 0; j < 8; j++) acc[j] = 0.f;
    const uint4* src8 = reinterpret_cast<const uint4*>(src);
    const int cidx = coff8 + tid;
    #pragma unroll 4
    for (int i = s; i < e; ++i) {
        int2 p = __ldg(&epair[i]);
        int c = p.x;
        float v = __int_as_float(p.y);
        uint4 hv = __ldg(&src8[(size_t)c * (DS / 8) + cidx]);
        float2 f0 = __half22float2(*reinterpret_cast<__half2*>(&hv.x));
        float2 f1 = __half22float2(*reinterpret_cast<__half2*>(&hv.y));
        float2 f2 = __half22float2(*reinterpret_cast<__half2*>(&hv.z));
        float2 f3 = __half22float2(*reinterpret_cast<__half2*>(&hv.w));
        acc[0] = fmaf(v, f0.x, acc[0]); acc[1] = fmaf(v, f0.y, acc[1]);
        acc[2] = fmaf(v, f1.x, acc[2]); acc[3] = fmaf(v, f1.y, acc[3]);
        acc[4] = fmaf(v, f2.x, acc[4]); acc[5] = fmaf(v, f2.y, acc[5]);
        acc[6] = fmaf(v, f3.x, acc[6]); acc[7] = fmaf(v, f3.y, acc[7]);
    }
    if (BIAS) {   // bias pointer pre-offset by caller to this column slice
        const float4* b4 = reinterpret_cast<const float4*>(bias) + tid * 2;
        float4 ba = __ldg(&b4[0]);
        float4 bb = __ldg(&b4[1]);
        acc[0] += ba.x; acc[1] += ba.y; acc[2] += ba.z; acc[3] += ba.w;
        acc[4] += bb.x; acc[5] += bb.y; acc[6] += bb.z; acc[7] += bb.w;
    }
    if (LEAKY) {
        #pragma unroll
        for (int j = 0; j < 8; j++) acc[j] = acc[j] >= 0.f ? acc[j] : 0.2f * acc[j];
    }
    if constexpr (sizeof(OutT) == 2) {
        uint4 pk;
        #pragma unroll
        for (int q = 0; q < 4; q++) {
            __half2 h = __floats2half2_rn(acc[2 * q], acc[2 * q + 1]);
            reinterpret_cast<uint32_t*>(&pk)[q] = *reinterpret_cast<uint32_t*>(&h);
        }
        reinterpret_cast<uint4*>(out)[(size_t)row * (DS / 8) + cidx] = pk;
    } else {
        float4* o4 = reinterpret_cast<float4*>(out) + (size_t)row * (DS / 4) + cidx * 2;
        o4[0] = make_float4(acc[0], acc[1], acc[2], acc[3]);
        o4[1] = make_float4(acc[4], acc[5], acc[6], acc[7]);
    }
}

// ---------------- fp16 tensor-core GEMM (128x128 tile, 256 thr, 4-stage) ----------------
// __launch_bounds__(256) WITHOUT min-blocks: natural regs -> 1 CTA/SM,
// leaving ~24K regs + ~150KB smem free so SPMM CTAs can co-reside.
#define BM 128
#define BN 128
#define BKK 32
#define LDA_S 40
#define LDB_S 136
constexpr int STG_A_BYTES = BM * LDA_S * 2;
constexpr int STG_B_BYTES = BKK * LDB_S * 2;
constexpr int STG_BYTES = STG_A_BYTES + STG_B_BYTES;
constexpr int GEMM_SMEM = 4 * STG_BYTES;             // 75776

__device__ __forceinline__ void cp16(uint32_t s, const void* g, int pbytes) {
    asm volatile("cp.async.cg.shared.global [%0], [%1], 16, %2;\n" ::"r"(s), "l"(g), "r"(pbytes));
}
__device__ __forceinline__ void ldsm_x4(uint32_t* r, uint32_t addr) {
    asm volatile("ldmatrix.sync.aligned.m8n8.x4.shared.b16 {%0,%1,%2,%3}, [%4];"
                 : "=r"(r[0]), "=r"(r[1]), "=r"(r[2]), "=r"(r[3]) : "r"(addr));
}
__device__ __forceinline__ void ldsm_x4_t(uint32_t* r, uint32_t addr) {
    asm volatile("ldmatrix.sync.aligned.m8n8.x4.trans.shared.b16 {%0,%1,%2,%3}, [%4];"
                 : "=r"(r[0]), "=r"(r[1]), "=r"(r[2]), "=r"(r[3]) : "r"(addr));
}
__device__ __forceinline__ void mma16816(float* c, const uint32_t* a, uint32_t b0, uint32_t b1) {
    asm volatile(
        "mma.sync.aligned.m16n8k16.row.col.f32.f16.f16.f32 "
        "{%0,%1,%2,%3}, {%4,%5,%6,%7}, {%8,%9}, {%0,%1,%2,%3};"
        : "+f"(c[0]), "+f"(c[1]), "+f"(c[2]), "+f"(c[3])
        : "r"(a[0]), "r"(a[1]), "r"(a[2]), "r"(a[3]), "r"(b0), "r"(b1));
}

// ldb/ldc: row strides (elements) of B and C, allowing N-sliced sub-GEMMs.
template <typename OutT, bool FUSE>
__global__ void __launch_bounds__(256) gemm_kernel(
    const __half* __restrict__ A, const __half* __restrict__ B, OutT* __restrict__ C,
    const float* __restrict__ bias, int M, int N, int K, int ldb, int ldc) {
    extern __shared__ __align__(128) char dsm[];
    const int tid = threadIdx.x, lane = tid & 31, wid = tid >> 5;
    const int rowBase = blockIdx.y * BM, colBase = blockIdx.x * BN;
    const int wm = (wid >> 1) * 32, wn = (wid & 1) * 64;

    const uint32_t sbase = (uint32_t)__cvta_generic_to_shared(dsm);

    auto load_tiles = [&](int stage, int k0) {
        uint32_t sAa = sbase + stage * STG_BYTES;
        uint32_t sBa = sAa + STG_A_BYTES;
        #pragma unroll
        for (int i = 0; i < 2; i++) {
            int c = tid + i * 256;
            int r = c >> 2, cw = c & 3;
            int gr = rowBase + r;
            const __half* gp = A + (size_t)min(gr, M - 1) * K + k0 + cw * 8;
            cp16(sAa + (r * LDA_S + cw * 8) * 2, gp, (gr < M) ? 16 : 0);
        }
        #pragma unroll
        for (int i = 0; i < 2; i++) {
            int c = tid + i * 256;
            int r = c >> 4, cw = c & 15;
            const __half* gp = B + (size_t)(k0 + r) * ldb + colBase + cw * 8;
            cp16(sBa + (r * LDB_S + cw * 8) * 2, gp, 16);
        }
        asm volatile("cp.async.commit_group;\n");
    };

    float acc[2][8][4];
    #pragma unroll
    for (int a = 0; a < 2; a++)
        #pragma unroll
        for (int b = 0; b < 8; b++)
            #pragma unroll
            for (int c = 0; c < 4; c++) acc[a][b][c] = 0.f;

    const int KT = K / BKK;
    load_tiles(0, 0);
    if (KT > 1) load_tiles(1, BKK);
    if (KT > 2) load_tiles(2, 2 * BKK);
    const int aRowL = lane & 15, aColL = (lane >> 4) << 3;
    const int bRowL = (lane & 7) + ((lane >> 3) & 1) * 8, bColL = (lane >> 4) << 3;

    int st = 0;
    for (int kt = 0; kt < KT; ++kt) {
        int pend = KT - 1 - kt; if (pend > 2) pend = 2;
        if (pend == 2)      asm volatile("cp.async.wait_group 2;\n");
        else if (pend == 1) asm volatile("cp.async.wait_group 1;\n");
        else                asm volatile("cp.async.wait_group 0;\n");
        __syncthreads();
        if (kt + 3 < KT) load_tiles((st + 3) & 3, (kt + 3) * BKK);
        uint32_t aB = sbase + st * STG_BYTES, bB = aB + STG_A_BYTES;
        #pragma unroll
        for (int ks = 0; ks < 2; ++ks) {
            int k0 = ks * 16;
            uint32_t af[2][4], bf[4][4];
            #pragma unroll
            for (int mt = 0; mt < 2; ++mt)
                ldsm_x4(af[mt], aB + ((wm + mt * 16 + aRowL) * LDA_S + k0 + aColL) * 2);
            #pragma unroll
            for (int np = 0; np < 4; ++np)
                ldsm_x4_t(bf[np], bB + ((k0 + bRowL) * LDB_S + wn + np * 16 + bColL) * 2);
            #pragma unroll
            for (int mt = 0; mt < 2; ++mt)
                #pragma unroll
                for (int nt = 0; nt < 8; ++nt)
                    mma16816(acc[mt][nt], af[mt], bf[nt >> 1][(nt & 1) * 2],
                             bf[nt >> 1][(nt & 1) * 2 + 1]);
        }
        st = (st + 1) & 3;
    }

    const int g = lane >> 2, cp2 = (lane & 3) * 2;
    #pragma unroll
    for (int mt = 0; mt < 2; ++mt) {
        #pragma unroll
        for (int nt = 0; nt < 8; ++nt) {
            int col = colBase + wn + nt * 8 + cp2;
            #pragma unroll
            for (int h = 0; h < 2; ++h) {
                int r = rowBase + wm + mt * 16 + g + h * 8;
                if (r < M) {
                    float v0 = acc[mt][nt][h * 2 + 0];
                    float v1 = acc[mt][nt][h * 2 + 1];
                    if (FUSE) {
                        v0 += __ldg(&bias[col]);
                        v1 += __ldg(&bias[col + 1]);
                        v0 = v0 >= 0.f ? v0 : 0.2f * v0;
                        v1 = v1 >= 0.f ? v1 : 0.2f * v1;
                    }
                    if constexpr (sizeof(OutT) == 2) {
                        *reinterpret_cast<__half2*>(&C[(size_t)r * ldc + col]) =
                            __floats2half2_rn(v0, v1);
                    } else {
                        *reinterpret_cast<float2*>(&C[(size_t)r * ldc + col]) =
                            make_float2(v0, v1);
                    }
                }
            }
        }
    }
}

// ---------------- launch ----------------
extern "C" void kernel_launch(void* const* d_in, const int* in_sizes, int n_in,
                              void* d_out, int out_size) {
    const float* x    = (const float*)d_in[0];
    const int*   erow = (const int*)d_in[1];
    const int*   ecol = (const int*)d_in[2];
    const float* eval = (const float*)d_in[3];
    const float* W0 = (const float*)d_in[4];
    const float* b0 = (const float*)d_in[5];
    const float* W1 = (const float*)d_in[6];
    const float* b1 = (const float*)d_in[7];
    const float* W2 = (const float*)d_in[8];
    const float* b2 = (const float*)d_in[9];
    const int E = in_sizes[1];

    int *cnt, *rowptr, *cursor;
    int2* epair;
    __half *xh, *t1, *h1, *s2, *h2, *s3, *W0h, *W1h, *W2h;
    cudaGetSymbolAddress((void**)&cnt, g_cnt);
    cudaGetSymbolAddress((void**)&rowptr, g_rowptr);
    cudaGetSymbolAddress((void**)&cursor, g_cursor);
    cudaGetSymbolAddress((void**)&epair, g_epair);
    cudaGetSymbolAddress((void**)&xh, g_xh);
    cudaGetSymbolAddress((void**)&t1, g_t1);
    cudaGetSymbolAddress((void**)&h1, g_h1);
    cudaGetSymbolAddress((void**)&s2, g_s2);
    cudaGetSymbolAddress((void**)&h2, g_h2);
    cudaGetSymbolAddress((void**)&s3, g_s3);
    cudaGetSymbolAddress((void**)&W0h, g_W0h);
    cudaGetSymbolAddress((void**)&W1h, g_W1h);
    cudaGetSymbolAddress((void**)&W2h, g_W2h);

    cudaFuncSetAttribute(gemm_kernel<__half, true>,
                         cudaFuncAttributeMaxDynamicSharedMemorySize, GEMM_SMEM);
    cudaFuncSetAttribute(gemm_kernel<__half, false>,
                         cudaFuncAttributeMaxDynamicSharedMemorySize, GEMM_SMEM);

    // side stream + events (host objects only; never destroyed so graph capture stays valid)
    cudaStream_t s1;
    cudaStreamCreate(&s1);
    cudaEvent_t evF, ev1, ev2, ev3, ev4, ev5, ev6;
    cudaEventCreateWithFlags(&evF, cudaEventDisableTiming);
    cudaEventCreateWithFlags(&ev1, cudaEventDisableTiming);
    cudaEventCreateWithFlags(&ev2, cudaEventDisableTiming);
    cudaEventCreateWithFlags(&ev3, cudaEventDisableTiming);
    cudaEventCreateWithFlags(&ev4, cudaEventDisableTiming);
    cudaEventCreateWithFlags(&ev5, cudaEventDisableTiming);
    cudaEventCreateWithFlags(&ev6, cudaEventDisableTiming);

    // ---- fork s1 early: W1/W2 conversion overlaps the CSR build ----
    cudaEventRecord(evF, 0);
    cudaStreamWaitEvent(s1, evF, 0);
    f2h2_kernel<<<512, 256, 0, s1>>>(W1, W1h, D1 * D2, W2, W2h, D2 * D3);

    // ---- main stream: CSR build + normalize (+W0 f2h) ----
    normh_count_kernel<<<N_NODES, 128>>>(x, xh, erow, cnt, E, W0, W0h, D0 * D1);
    scan_kernel<<<1, 1024>>>(cnt, rowptr, cursor);
    scatter_kernel<<<(E + 255) / 256, 256>>>(erow, ecol, eval, cursor, epair, cnt, E);

    // ---- layer 1: M-split; spmm1_B overlaps gemm1_A ----
    spmm_h_kernel<D0, false, false, __half>
        <<<M_HALF, D0 / 8>>>(rowptr, epair, xh, nullptr, t1, 0, 0);
    cudaEventRecord(ev1, 0);
    cudaStreamWaitEvent(s1, ev1, 0);
    gemm_kernel<__half, true>
        <<<dim3(D1 / BN, (M_HALF + BM - 1) / BM), 256, GEMM_SMEM, s1>>>(
            t1, W0h, h1, b0, M_HALF, D1, D0, D1, D1);
    cudaEventRecord(ev2, s1);
    spmm_h_kernel<D0, false, false, __half>
        <<<N_NODES - M_HALF, D0 / 8>>>(rowptr, epair, xh, nullptr, t1, M_HALF, 0);
    gemm_kernel<__half, true>
        <<<dim3(D1 / BN, (N_NODES - M_HALF + BM - 1) / BM), 256, GEMM_SMEM>>>(
            t1 + (size_t)M_HALF * D0, W0h, h1 + (size_t)M_HALF * D1, b0,
            N_NODES - M_HALF, D1, D0, D1, D1);
    cudaStreamWaitEvent(0, ev2, 0);          // join: h1 complete

    // ---- layer 2: N-split gemm2; spmm2_colA overlaps gemm2_NB ----
    gemm_kernel<__half, false>
        <<<dim3((D2 / 2) / BN, (N_NODES + BM - 1) / BM), 256, GEMM_SMEM>>>(
            h1, W1h, s2, nullptr, N_NODES, D2 / 2, D1, D2, D2);
    cudaEventRecord(ev3, 0);
    cudaStreamWaitEvent(s1, ev3, 0);
    spmm_h_kernel<D2, true, true, __half>
        <<<N_NODES, 64, 0, s1>>>(rowptr, epair, s2, b1, h2, 0, 0);
    cudaEventRecord(ev4, s1);
    gemm_kernel<__half, false>
        <<<dim3((D2 / 2) / BN, (N_NODES + BM - 1) / BM), 256, GEMM_SMEM>>>(
            h1, W1h + D2 / 2, s2 + D2 / 2, nullptr, N_NODES, D2 / 2, D1, D2, D2);
    spmm_h_kernel<D2, true, true, __half>
        <<<N_NODES, 64>>>(rowptr, epair, s2, b1 + D2 / 2, h2, 0, (D2 / 2) / 8);
    cudaStreamWaitEvent(0, ev4, 0);          // join: h2 complete

    // ---- layer 3: N-split gemm3; spmm3_colA overlaps gemm3_NB ----
    gemm_kernel<__half, false>
        <<<dim3((D3 / 2) / BN, (N_NODES + BM - 1) / BM), 256, GEMM_SMEM>>>(
            h2, W2h, s3, nullptr, N_NODES, D3 / 2, D2, D3, D3);
    cudaEventRecord(ev5, 0);
    cudaStreamWaitEvent(s1, ev5, 0);
    spmm_h_kernel<D3, true, false, float>
        <<<N_NODES, 32, 0, s1>>>(rowptr, epair, s3, b2, (float*)d_out, 0, 0);
    cudaEventRecord(ev6, s1);
    gemm_kernel<__half, false>
        <<<dim3((D3 / 2) / BN, (N_NODES + BM - 1) / BM), 256, GEMM_SMEM>>>(
            h2, W2h + D3 / 2, s3 + D3 / 2, nullptr, N_NODES, D3 / 2, D2, D3, D3);
    spmm_h_kernel<D3, true, false, float>
        <<<N_NODES, 32>>>(rowptr, epair, s3, b2 + D3 / 2, (float*)d_out, 0, (D3 / 2) / 8);
    cudaStreamWaitEvent(0, ev6, 0);          // join: d_out complete on stream 0
}

// round 16
// speedup vs baseline: 1.0046x; 1.0046x over previous
#include <cuda_runtime.h>
#include <cuda_fp16.h>
#include <cstdint>
#include <cstddef>

// ---------------- problem constants ----------------
#define N_NODES 50000
#define N_EDGES 1600000
constexpr int D0 = 512, D1 = 2048, D2 = 1024, D3 = 512;
constexpr int M_HALF = 25000;

// ---------------- device scratch ----------------
__device__ int    g_cnt[N_NODES];            // zero at load; re-zeroed by scatter each call
__device__ int    g_rowptr[N_NODES + 1];
__device__ int    g_cursor[N_NODES];
__device__ int2   g_epair[N_EDGES];
__device__ __half g_xh[N_NODES * D0];
__device__ __half g_t1[N_NODES * D0];
__device__ __half g_h1[(size_t)N_NODES * D1];
__device__ __half g_s2[N_NODES * D2];
__device__ __half g_h2[N_NODES * D2];
__device__ __half g_s3[N_NODES * D3];
__device__ __half g_W0h[D0 * D1];
__device__ __half g_W1h[D1 * D2];
__device__ __half g_W2h[D2 * D3];

// ---------------- normalize + fp16 convert + degree count + W0 f2h (fused) ----------------
__global__ void normh_count_kernel(const float* __restrict__ x, __half* __restrict__ xh,
                                   const int* __restrict__ erow, int* __restrict__ cnt, int E,
                                   const float* __restrict__ W, __half* __restrict__ Wh, int nW) {
    int row = blockIdx.x, tid = threadIdx.x;
    const float4* x4 = reinterpret_cast<const float4*>(x);
    float4 v = x4[(size_t)row * (D0 / 4) + tid];
    float ss = v.x * v.x + v.y * v.y + v.z * v.z + v.w * v.w;
    #pragma unroll
    for (int o = 16; o; o >>= 1) ss += __shfl_xor_sync(0xffffffffu, ss, o);
    __shared__ float sw[4];
    __shared__ float s_inv;
    if ((tid & 31) == 0) sw[tid >> 5] = ss;
    __syncthreads();
    if (tid == 0) {
        float t = sw[0] + sw[1] + sw[2] + sw[3];
        s_inv = 1.0f / fmaxf(sqrtf(t), 1e-12f);
    }
    __syncthreads();
    float inv = s_inv;
    __half2* o2 = reinterpret_cast<__half2*>(xh) + (size_t)row * (D0 / 2) + tid * 2;
    o2[0] = __floats2half2_rn(v.x * inv, v.y * inv);
    o2[1] = __floats2half2_rn(v.z * inv, v.w * inv);
    int gstride = gridDim.x * blockDim.x;
    int g0 = blockIdx.x * blockDim.x + tid;
    for (int i = g0; i < E; i += gstride)
        atomicAdd(&cnt[erow[i]], 1);
    for (int i = g0; i < nW; i += gstride)
        Wh[i] = __float2half_rn(W[i]);
}

__global__ void scan_kernel(const int* __restrict__ cnt, int* __restrict__ rowptr,
                            int* __restrict__ cursor) {
    __shared__ int sh[1024];
    __shared__ int carry;
    int t = threadIdx.x;
    if (t == 0) { carry = 0; rowptr[0] = 0; cursor[0] = 0; }
    __syncthreads();
    for (int base = 0; base < N_NODES; base += 1024) {
        int i = base + t;
        int v = (i < N_NODES) ? cnt[i] : 0;
        sh[t] = v;
        __syncthreads();
        #pragma unroll
        for (int off = 1; off < 1024; off <<= 1) {
            int u = (t >= off) ? sh[t - off] : 0;
            __syncthreads();
            sh[t] += u;
            __syncthreads();
        }
        if (i < N_NODES) {
            int val = carry + sh[t];
            rowptr[i + 1] = val;
            if (i + 1 < N_NODES) cursor[i + 1] = val;
        }
        __syncthreads();
        if (t == 0) carry += sh[1023];
        __syncthreads();
    }
}

__global__ void scatter_kernel(const int* __restrict__ erow, const int* __restrict__ ecol,
                               const float* __restrict__ eval, int* __restrict__ cursor,
                               int2* __restrict__ epair, int* __restrict__ cnt, int E) {
    int gstride = gridDim.x * blockDim.x;
    int g0 = blockIdx.x * blockDim.x + threadIdx.x;
    for (int i = g0; i < E; i += gstride) {
        int r = erow[i];
        int p = atomicAdd(&cursor[r], 1);
        epair[p] = make_int2(ecol[i], __float_as_int(eval[i]));
    }
    for (int i = g0; i < N_NODES; i += gstride)
        cnt[i] = 0;
}

// convert W1 and W2 in one launch (side stream, overlapped with CSR build)
__global__ void f2h2_kernel(const float* __restrict__ in1, __half* __restrict__ out1, int n1,
                            const float* __restrict__ in2, __half* __restrict__ out2, int n2) {
    int gstride = gridDim.x * blockDim.x;
    int g0 = blockIdx.x * blockDim.x + threadIdx.x;
    for (int i = g0; i < n1; i += gstride) out1[i] = __float2half_rn(in1[i]);
    for (int i = g0; i < n2; i += gstride) out2[i] = __float2half_rn(in2[i]);
}

// ---------------- SPMM (fp16 src, packed edges, FFMA accum) ----------------
// DS = full row width (halves) of src AND out. blockDim covers a column slice;
// row0 = output row offset, coff8 = column offset in uint4 (8-half) units.
template <int DS, bool BIAS, bool LEAKY, typename OutT>
__global__ void spmm_h_kernel(const int* __restrict__ rowptr, const int2* __restrict__ epair,
                              const __half* __restrict__ src,
                              const float* __restrict__ bias, OutT* __restrict__ out,
                              int row0, int coff8) {
    const int row = blockIdx.x + row0;
    const int tid = threadIdx.x;
    int s = __ldg(&rowptr[row]), e = __ldg(&rowptr[row + 1]);
    float acc[8];
    #pragma unroll
    for (int j = 0; j < 8; j++) acc[j] = 0.f;
    const uint4* src8 = reinterpret_cast<const uint4*>(src);
    const int cidx = coff8 + tid;
    #pragma unroll 4
    for (int i = s; i < e; ++i) {
        int2 p = __ldg(&epair[i]);
        int c = p.x;
        float v = __int_as_float(p.y);
        uint4 hv = __ldg(&src8[(size_t)c * (DS / 8) + cidx]);
        float2 f0 = __half22float2(*reinterpret_cast<__half2*>(&hv.x));
        float2 f1 = __half22float2(*reinterpret_cast<__half2*>(&hv.y));
        float2 f2 = __half22float2(*reinterpret_cast<__half2*>(&hv.z));
        float2 f3 = __half22float2(*reinterpret_cast<__half2*>(&hv.w));
        acc[0] = fmaf(v, f0.x, acc[0]); acc[1] = fmaf(v, f0.y, acc[1]);
        acc[2] = fmaf(v, f1.x, acc[2]); acc[3] = fmaf(v, f1.y, acc[3]);
        acc[4] = fmaf(v, f2.x, acc[4]); acc[5] = fmaf(v, f2.y, acc[5]);
        acc[6] = fmaf(v, f3.x, acc[6]); acc[7] = fmaf(v, f3.y, acc[7]);
    }
    if (BIAS) {   // bias pointer pre-offset by caller to this column slice
        const float4* b4 = reinterpret_cast<const float4*>(bias) + tid * 2;
        float4 ba = __ldg(&b4[0]);
        float4 bb = __ldg(&b4[1]);
        acc[0] += ba.x; acc[1] += ba.y; acc[2] += ba.z; acc[3] += ba.w;
        acc[4] += bb.x; acc[5] += bb.y; acc[6] += bb.z; acc[7] += bb.w;
    }
    if (LEAKY) {
        #pragma unroll
        for (int j = 0; j < 8; j++) acc[j] = acc[j] >= 0.f ? acc[j] : 0.2f * acc[j];
    }
    if constexpr (sizeof(OutT) == 2) {
        uint4 pk;
        #pragma unroll
        for (int q = 0; q < 4; q++) {
            __half2 h = __floats2half2_rn(acc[2 * q], acc[2 * q + 1]);
            reinterpret_cast<uint32_t*>(&pk)[q] = *reinterpret_cast<uint32_t*>(&h);
        }
        reinterpret_cast<uint4*>(out)[(size_t)row * (DS / 8) + cidx] = pk;
    } else {
        float4* o4 = reinterpret_cast<float4*>(out) + (size_t)row * (DS / 4) + cidx * 2;
        o4[0] = make_float4(acc[0], acc[1], acc[2], acc[3]);
        o4[1] = make_float4(acc[4], acc[5], acc[6], acc[7]);
    }
}

// ---------------- fp16 tensor-core GEMM (128x128 tile, 256 thr, occ 2, 4-stage) ----------------
#define BM 128
#define BN 128
#define BKK 32
#define LDA_S 40
#define LDB_S 136
constexpr int STG_A_BYTES = BM * LDA_S * 2;
constexpr int STG_B_BYTES = BKK * LDB_S * 2;
constexpr int STG_BYTES = STG_A_BYTES + STG_B_BYTES;
constexpr int GEMM_SMEM = 4 * STG_BYTES;             // 75776

__device__ __forceinline__ void cp16(uint32_t s, const void* g, int pbytes) {
    asm volatile("cp.async.cg.shared.global [%0], [%1], 16, %2;\n" ::"r"(s), "l"(g), "r"(pbytes));
}
__device__ __forceinline__ void ldsm_x4(uint32_t* r, uint32_t addr) {
    asm volatile("ldmatrix.sync.aligned.m8n8.x4.shared.b16 {%0,%1,%2,%3}, [%4];"
                 : "=r"(r[0]), "=r"(r[1]), "=r"(r[2]), "=r"(r[3]) : "r"(addr));
}
__device__ __forceinline__ void ldsm_x4_t(uint32_t* r, uint32_t addr) {
    asm volatile("ldmatrix.sync.aligned.m8n8.x4.trans.shared.b16 {%0,%1,%2,%3}, [%4];"
                 : "=r"(r[0]), "=r"(r[1]), "=r"(r[2]), "=r"(r[3]) : "r"(addr));
}
__device__ __forceinline__ void mma16816(float* c, const uint32_t* a, uint32_t b0, uint32_t b1) {
    asm volatile(
        "mma.sync.aligned.m16n8k16.row.col.f32.f16.f16.f32 "
        "{%0,%1,%2,%3}, {%4,%5,%6,%7}, {%8,%9}, {%0,%1,%2,%3};"
        : "+f"(c[0]), "+f"(c[1]), "+f"(c[2]), "+f"(c[3])
        : "r"(a[0]), "r"(a[1]), "r"(a[2]), "r"(a[3]), "r"(b0), "r"(b1));
}

// ldb/ldc: row strides (elements) of B and C, allowing N-sliced sub-GEMMs.
template <typename OutT, bool FUSE>
__global__ void __launch_bounds__(256, 2) gemm_kernel(
    const __half* __restrict__ A, const __half* __restrict__ B, OutT* __restrict__ C,
    const float* __restrict__ bias, int M, int N, int K, int ldb, int ldc) {
    extern __shared__ __align__(128) char dsm[];
    const int tid = threadIdx.x, lane = tid & 31, wid = tid >> 5;
    const int rowBase = blockIdx.y * BM, colBase = blockIdx.x * BN;
    const int wm = (wid >> 1) * 32, wn = (wid & 1) * 64;

    const uint32_t sbase = (uint32_t)__cvta_generic_to_shared(dsm);

    auto load_tiles = [&](int stage, int k0) {
        uint32_t sAa = sbase + stage * STG_BYTES;
        uint32_t sBa = sAa + STG_A_BYTES;
        #pragma unroll
        for (int i = 0; i < 2; i++) {
            int c = tid + i * 256;
            int r = c >> 2, cw = c & 3;
            int gr = rowBase + r;
            const __half* gp = A + (size_t)min(gr, M - 1) * K + k0 + cw * 8;
            cp16(sAa + (r * LDA_S + cw * 8) * 2, gp, (gr < M) ? 16 : 0);
        }
        #pragma unroll
        for (int i = 0; i < 2; i++) {
            int c = tid + i * 256;
            int r = c >> 4, cw = c & 15;
            const __half* gp = B + (size_t)(k0 + r) * ldb + colBase + cw * 8;
            cp16(sBa + (r * LDB_S + cw * 8) * 2, gp, 16);
        }
        asm volatile("cp.async.commit_group;\n");
    };

    float acc[2][8][4];
    #pragma unroll
    for (int a = 0; a < 2; a++)
        #pragma unroll
        for (int b = 0; b < 8; b++)
            #pragma unroll
            for (int c = 0; c < 4; c++) acc[a][b][c] = 0.f;

    const int KT = K / BKK;
    load_tiles(0, 0);
    if (KT > 1) load_tiles(1, BKK);
    if (KT > 2) load_tiles(2, 2 * BKK);
    const int aRowL = lane & 15, aColL = (lane >> 4) << 3;
    const int bRowL = (lane & 7) + ((lane >> 3) & 1) * 8, bColL = (lane >> 4) << 3;

    int st = 0;
    for (int kt = 0; kt < KT; ++kt) {
        int pend = KT - 1 - kt; if (pend > 2) pend = 2;
        if (pend == 2)      asm volatile("cp.async.wait_group 2;\n");
        else if (pend == 1) asm volatile("cp.async.wait_group 1;\n");
        else                asm volatile("cp.async.wait_group 0;\n");
        __syncthreads();
        if (kt + 3 < KT) load_tiles((st + 3) & 3, (kt + 3) * BKK);
        uint32_t aB = sbase + st * STG_BYTES, bB = aB + STG_A_BYTES;
        #pragma unroll
        for (int ks = 0; ks < 2; ++ks) {
            int k0 = ks * 16;
            uint32_t af[2][4], bf[4][4];
            #pragma unroll
            for (int mt = 0; mt < 2; ++mt)
                ldsm_x4(af[mt], aB + ((wm + mt * 16 + aRowL) * LDA_S + k0 + aColL) * 2);
            #pragma unroll
            for (int np = 0; np < 4; ++np)
                ldsm_x4_t(bf[np], bB + ((k0 + bRowL) * LDB_S + wn + np * 16 + bColL) * 2);
            #pragma unroll
            for (int mt = 0; mt < 2; ++mt)
                #pragma unroll
                for (int nt = 0; nt < 8; ++nt)
                    mma16816(acc[mt][nt], af[mt], bf[nt >> 1][(nt & 1) * 2],
                             bf[nt >> 1][(nt & 1) * 2 + 1]);
        }
        st = (st + 1) & 3;
    }

    const int g = lane >> 2, cp2 = (lane & 3) * 2;
    #pragma unroll
    for (int mt = 0; mt < 2; ++mt) {
        #pragma unroll
        for (int nt = 0; nt < 8; ++nt) {
            int col = colBase + wn + nt * 8 + cp2;
            #pragma unroll
            for (int h = 0; h < 2; ++h) {
                int r = rowBase + wm + mt * 16 + g + h * 8;
                if (r < M) {
                    float v0 = acc[mt][nt][h * 2 + 0];
                    float v1 = acc[mt][nt][h * 2 + 1];
                    if (FUSE) {
                        v0 += __ldg(&bias[col]);
                        v1 += __ldg(&bias[col + 1]);
                        v0 = v0 >= 0.f ? v0 : 0.2f * v0;
                        v1 = v1 >= 0.f ? v1 : 0.2f * v1;
                    }
                    if constexpr (sizeof(OutT) == 2) {
                        *reinterpret_cast<__half2*>(&C[(size_t)r * ldc + col]) =
                            __floats2half2_rn(v0, v1);
                    } else {
                        *reinterpret_cast<float2*>(&C[(size_t)r * ldc + col]) =
                            make_float2(v0, v1);
                    }
                }
            }
        }
    }
}

// ---------------- launch ----------------
extern "C" void kernel_launch(void* const* d_in, const int* in_sizes, int n_in,
                              void* d_out, int out_size) {
    const float* x    = (const float*)d_in[0];
    const int*   erow = (const int*)d_in[1];
    const int*   ecol = (const int*)d_in[2];
    const float* eval = (const float*)d_in[3];
    const float* W0 = (const float*)d_in[4];
    const float* b0 = (const float*)d_in[5];
    const float* W1 = (const float*)d_in[6];
    const float* b1 = (const float*)d_in[7];
    const float* W2 = (const float*)d_in[8];
    const float* b2 = (const float*)d_in[9];
    const int E = in_sizes[1];

    int *cnt, *rowptr, *cursor;
    int2* epair;
    __half *xh, *t1, *h1, *s2, *h2, *s3, *W0h, *W1h, *W2h;
    cudaGetSymbolAddress((void**)&cnt, g_cnt);
    cudaGetSymbolAddress((void**)&rowptr, g_rowptr);
    cudaGetSymbolAddress((void**)&cursor, g_cursor);
    cudaGetSymbolAddress((void**)&epair, g_epair);
    cudaGetSymbolAddress((void**)&xh, g_xh);
    cudaGetSymbolAddress((void**)&t1, g_t1);
    cudaGetSymbolAddress((void**)&h1, g_h1);
    cudaGetSymbolAddress((void**)&s2, g_s2);
    cudaGetSymbolAddress((void**)&h2, g_h2);
    cudaGetSymbolAddress((void**)&s3, g_s3);
    cudaGetSymbolAddress((void**)&W0h, g_W0h);
    cudaGetSymbolAddress((void**)&W1h, g_W1h);
    cudaGetSymbolAddress((void**)&W2h, g_W2h);

    cudaFuncSetAttribute(gemm_kernel<__half, true>,
                         cudaFuncAttributeMaxDynamicSharedMemorySize, GEMM_SMEM);
    cudaFuncSetAttribute(gemm_kernel<__half, false>,
                         cudaFuncAttributeMaxDynamicSharedMemorySize, GEMM_SMEM);

    // side stream + events (host objects only; never destroyed so graph capture stays valid)
    cudaStream_t s1;
    cudaStreamCreate(&s1);
    cudaEvent_t evF, ev1, ev2, ev3, ev4, ev5, ev6;
    cudaEventCreateWithFlags(&evF, cudaEventDisableTiming);
    cudaEventCreateWithFlags(&ev1, cudaEventDisableTiming);
    cudaEventCreateWithFlags(&ev2, cudaEventDisableTiming);
    cudaEventCreateWithFlags(&ev3, cudaEventDisableTiming);
    cudaEventCreateWithFlags(&ev4, cudaEventDisableTiming);
    cudaEventCreateWithFlags(&ev5, cudaEventDisableTiming);
    cudaEventCreateWithFlags(&ev6, cudaEventDisableTiming);

    // ---- fork s1 early: W1/W2 conversion overlaps the CSR build ----
    cudaEventRecord(evF, 0);
    cudaStreamWaitEvent(s1, evF, 0);
    f2h2_kernel<<<512, 256, 0, s1>>>(W1, W1h, D1 * D2, W2, W2h, D2 * D3);

    // ---- main stream: CSR build + normalize (+W0 f2h) ----
    normh_count_kernel<<<N_NODES, 128>>>(x, xh, erow, cnt, E, W0, W0h, D0 * D1);
    scan_kernel<<<1, 1024>>>(cnt, rowptr, cursor);
    scatter_kernel<<<(E + 255) / 256, 256>>>(erow, ecol, eval, cursor, epair, cnt, E);

    // ---- layer 1: M-split; spmm1_B overlaps gemm1_A ----
    spmm_h_kernel<D0, false, false, __half>
        <<<M_HALF, D0 / 8>>>(rowptr, epair, xh, nullptr, t1, 0, 0);
    cudaEventRecord(ev1, 0);
    cudaStreamWaitEvent(s1, ev1, 0);
    gemm_kernel<__half, true>
        <<<dim3(D1 / BN, (M_HALF + BM - 1) / BM), 256, GEMM_SMEM, s1>>>(
            t1, W0h, h1, b0, M_HALF, D1, D0, D1, D1);
    cudaEventRecord(ev2, s1);
    spmm_h_kernel<D0, false, false, __half>
        <<<N_NODES - M_HALF, D0 / 8>>>(rowptr, epair, xh, nullptr, t1, M_HALF, 0);
    gemm_kernel<__half, true>
        <<<dim3(D1 / BN, (N_NODES - M_HALF + BM - 1) / BM), 256, GEMM_SMEM>>>(
            t1 + (size_t)M_HALF * D0, W0h, h1 + (size_t)M_HALF * D1, b0,
            N_NODES - M_HALF, D1, D0, D1, D1);
    cudaStreamWaitEvent(0, ev2, 0);          // join: h1 complete

    // ---- layer 2: N-split gemm2; spmm2_colA overlaps gemm2_NB ----
    gemm_kernel<__half, false>
        <<<dim3((D2 / 2) / BN, (N_NODES + BM - 1) / BM), 256, GEMM_SMEM>>>(
            h1, W1h, s2, nullptr, N_NODES, D2 / 2, D1, D2, D2);
    cudaEventRecord(ev3, 0);
    cudaStreamWaitEvent(s1, ev3, 0);
    spmm_h_kernel<D2, true, true, __half>
        <<<N_NODES, 64, 0, s1>>>(rowptr, epair, s2, b1, h2, 0, 0);
    cudaEventRecord(ev4, s1);
    gemm_kernel<__half, false>
        <<<dim3((D2 / 2) / BN, (N_NODES + BM - 1) / BM), 256, GEMM_SMEM>>>(
            h1, W1h + D2 / 2, s2 + D2 / 2, nullptr, N_NODES, D2 / 2, D1, D2, D2);
    spmm_h_kernel<D2, true, true, __half>
        <<<N_NODES, 64>>>(rowptr, epair, s2, b1 + D2 / 2, h2, 0, (D2 / 2) / 8);
    cudaStreamWaitEvent(0, ev4, 0);          // join: h2 complete

    // ---- layer 3: N-split gemm3; spmm3_colA overlaps gemm3_NB ----
    gemm_kernel<__half, false>
        <<<dim3((D3 / 2) / BN, (N_NODES + BM - 1) / BM), 256, GEMM_SMEM>>>(
            h2, W2h, s3, nullptr, N_NODES, D3 / 2, D2, D3, D3);
    cudaEventRecord(ev5, 0);
    cudaStreamWaitEvent(s1, ev5, 0);
    spmm_h_kernel<D3, true, false, float>
        <<<N_NODES, 32, 0, s1>>>(rowptr, epair, s3, b2, (float*)d_out, 0, 0);
    cudaEventRecord(ev6, s1);
    gemm_kernel<__half, false>
        <<<dim3((D3 / 2) / BN, (N_NODES + BM - 1) / BM), 256, GEMM_SMEM>>>(
            h2, W2h + D3 / 2, s3 + D3 / 2, nullptr, N_NODES, D3 / 2, D2, D3, D3);
    spmm_h_kernel<D3, true, false, float>
        <<<N_NODES, 32>>>(rowptr, epair, s3, b2 + D3 / 2, (float*)d_out, 0, (D3 / 2) / 8);
    cudaStreamWaitEvent(0, ev6, 0);          // join: d_out complete on stream 0
}

// round 17
// speedup vs baseline: 1.0672x; 1.0623x over previous
#include <cuda_runtime.h>
#include <cuda_fp16.h>
#include <cstdint>
#include <cstddef>

// ---------------- problem constants ----------------
#define N_NODES 50000
#define N_EDGES 1600000
constexpr int D0 = 512, D1 = 2048, D2 = 1024, D3 = 512;
constexpr int M_HALF = 25000;

// ---------------- device scratch ----------------
__device__ int    g_cnt[N_NODES];            // zero at load; re-zeroed by scatter each call
__device__ int    g_rowptr[N_NODES + 1];
__device__ int    g_cursor[N_NODES];
__device__ int2   g_epair[N_EDGES];
__device__ __half g_xh[N_NODES * D0];
__device__ __half g_t1[N_NODES * D0];
__device__ __half g_h1[(size_t)N_NODES * D1];
__device__ __half g_s2[N_NODES * D2];
__device__ __half g_h2[N_NODES * D2];
__device__ __half g_s3[N_NODES * D3];
__device__ __half g_W0h[D0 * D1];
__device__ __half g_W1h[D1 * D2];
__device__ __half g_W2h[D2 * D3];

// ---------------- normalize + fp16 convert + degree count + W0 f2h (fused) ----------------
__global__ void normh_count_kernel(const float* __restrict__ x, __half* __restrict__ xh,
                                   const int* __restrict__ erow, int* __restrict__ cnt, int E,
                                   const float* __restrict__ W, __half* __restrict__ Wh, int nW) {
    int row = blockIdx.x, tid = threadIdx.x;
    const float4* x4 = reinterpret_cast<const float4*>(x);
    float4 v = x4[(size_t)row * (D0 / 4) + tid];
    float ss = v.x * v.x + v.y * v.y + v.z * v.z + v.w * v.w;
    #pragma unroll
    for (int o = 16; o; o >>= 1) ss += __shfl_xor_sync(0xffffffffu, ss, o);
    __shared__ float sw[4];
    __shared__ float s_inv;
    if ((tid & 31) == 0) sw[tid >> 5] = ss;
    __syncthreads();
    if (tid == 0) {
        float t = sw[0] + sw[1] + sw[2] + sw[3];
        s_inv = 1.0f / fmaxf(sqrtf(t), 1e-12f);
    }
    __syncthreads();
    float inv = s_inv;
    __half2* o2 = reinterpret_cast<__half2*>(xh) + (size_t)row * (D0 / 2) + tid * 2;
    o2[0] = __floats2half2_rn(v.x * inv, v.y * inv);
    o2[1] = __floats2half2_rn(v.z * inv, v.w * inv);
    int gstride = gridDim.x * blockDim.x;
    int g0 = blockIdx.x * blockDim.x + tid;
    for (int i = g0; i < E; i += gstride)
        atomicAdd(&cnt[erow[i]], 1);
    for (int i = g0; i < nW; i += gstride)
        Wh[i] = __float2half_rn(W[i]);
}

// ---------------- two-level shuffle scan (4 barriers per 1024-chunk) ----------------
__global__ void scan_kernel(const int* __restrict__ cnt, int* __restrict__ rowptr,
                            int* __restrict__ cursor) {
    __shared__ int wsum[32];
    __shared__ int carry;
    const int t = threadIdx.x, lane = t & 31, wid = t >> 5;
    if (t == 0) { carry = 0; rowptr[0] = 0; cursor[0] = 0; }
    __syncthreads();
    for (int base = 0; base < N_NODES; base += 1024) {
        int i = base + t;
        int x = (i < N_NODES) ? cnt[i] : 0;
        #pragma unroll
        for (int o = 1; o < 32; o <<= 1) {
            int u = __shfl_up_sync(0xffffffffu, x, o);
            if (lane >= o) x += u;
        }
        if (lane == 31) wsum[wid] = x;
        __syncthreads();
        if (wid == 0) {
            int s = wsum[lane];
            #pragma unroll
            for (int o = 1; o < 32; o <<= 1) {
                int u = __shfl_up_sync(0xffffffffu, s, o);
                if (lane >= o) s += u;
            }
            wsum[lane] = s;
        }
        __syncthreads();
        int incl = x + carry + (wid > 0 ? wsum[wid - 1] : 0);
        if (i < N_NODES) {
            rowptr[i + 1] = incl;
            if (i + 1 < N_NODES) cursor[i + 1] = incl;
        }
        __syncthreads();                 // everyone done reading carry/wsum
        if (t == 0) carry += wsum[31];
        __syncthreads();
    }
}

__global__ void scatter_kernel(const int* __restrict__ erow, const int* __restrict__ ecol,
                               const float* __restrict__ eval, int* __restrict__ cursor,
                               int2* __restrict__ epair, int* __restrict__ cnt, int E) {
    int gstride = gridDim.x * blockDim.x;
    int g0 = blockIdx.x * blockDim.x + threadIdx.x;
    for (int i = g0; i < E; i += gstride) {
        int r = erow[i];
        int p = atomicAdd(&cursor[r], 1);
        epair[p] = make_int2(ecol[i], __float_as_int(eval[i]));
    }
    for (int i = g0; i < N_NODES; i += gstride)
        cnt[i] = 0;
}

// convert W1 and W2 in one launch (side stream, overlapped with CSR build)
__global__ void f2h2_kernel(const float* __restrict__ in1, __half* __restrict__ out1, int n1,
                            const float* __restrict__ in2, __half* __restrict__ out2, int n2) {
    int gstride = gridDim.x * blockDim.x;
    int g0 = blockIdx.x * blockDim.x + threadIdx.x;
    for (int i = g0; i < n1; i += gstride) out1[i] = __float2half_rn(in1[i]);
    for (int i = g0; i < n2; i += gstride) out2[i] = __float2half_rn(in2[i]);
}

// ---------------- SPMM (fp16 src, packed edges, FFMA accum) ----------------
// DS = full row width (halves) of src AND out. blockDim covers a column slice;
// row0 = output row offset, coff8 = column offset in uint4 (8-half) units.
template <int DS, bool BIAS, bool LEAKY, typename OutT>
__global__ void spmm_h_kernel(const int* __restrict__ rowptr, const int2* __restrict__ epair,
                              const __half* __restrict__ src,
                              const float* __restrict__ bias, OutT* __restrict__ out,
                              int row0, int coff8) {
    const int row = blockIdx.x + row0;
    const int tid = threadIdx.x;
    int s = __ldg(&rowptr[row]), e = __ldg(&rowptr[row + 1]);
    float acc[8];
    #pragma unroll
    for (int j = 0; j < 8; j++) acc[j] = 0.f;
    const uint4* src8 = reinterpret_cast<const uint4*>(src);
    const int cidx = coff8 + tid;
    #pragma unroll 4
    for (int i = s; i < e; ++i) {
        int2 p = __ldg(&epair[i]);
        int c = p.x;
        float v = __int_as_float(p.y);
        uint4 hv = __ldg(&src8[(size_t)c * (DS / 8) + cidx]);
        float2 f0 = __half22float2(*reinterpret_cast<__half2*>(&hv.x));
        float2 f1 = __half22float2(*reinterpret_cast<__half2*>(&hv.y));
        float2 f2 = __half22float2(*reinterpret_cast<__half2*>(&hv.z));
        float2 f3 = __half22float2(*reinterpret_cast<__half2*>(&hv.w));
        acc[0] = fmaf(v, f0.x, acc[0]); acc[1] = fmaf(v, f0.y, acc[1]);
        acc[2] = fmaf(v, f1.x, acc[2]); acc[3] = fmaf(v, f1.y, acc[3]);
        acc[4] = fmaf(v, f2.x, acc[4]); acc[5] = fmaf(v, f2.y, acc[5]);
        acc[6] = fmaf(v, f3.x, acc[6]); acc[7] = fmaf(v, f3.y, acc[7]);
    }
    if (BIAS) {   // bias pointer pre-offset by caller to this column slice
        const float4* b4 = reinterpret_cast<const float4*>(bias) + tid * 2;
        float4 ba = __ldg(&b4[0]);
        float4 bb = __ldg(&b4[1]);
        acc[0] += ba.x; acc[1] += ba.y; acc[2] += ba.z; acc[3] += ba.w;
        acc[4] += bb.x; acc[5] += bb.y; acc[6] += bb.z; acc[7] += bb.w;
    }
    if (LEAKY) {
        #pragma unroll
        for (int j = 0; j < 8; j++) acc[j] = acc[j] >= 0.f ? acc[j] : 0.2f * acc[j];
    }
    if constexpr (sizeof(OutT) == 2) {
        uint4 pk;
        #pragma unroll
        for (int q = 0; q < 4; q++) {
            __half2 h = __floats2half2_rn(acc[2 * q], acc[2 * q + 1]);
            reinterpret_cast<uint32_t*>(&pk)[q] = *reinterpret_cast<uint32_t*>(&h);
        }
        reinterpret_cast<uint4*>(out)[(size_t)row * (DS / 8) + cidx] = pk;
    } else {
        float4* o4 = reinterpret_cast<float4*>(out) + (size_t)row * (DS / 4) + cidx * 2;
        o4[0] = make_float4(acc[0], acc[1], acc[2], acc[3]);
        o4[1] = make_float4(acc[4], acc[5], acc[6], acc[7]);
    }
}

// ---------------- fp16 tensor-core GEMM (128x128 tile, 256 thr, occ 2, 4-stage) ----------------
#define BM 128
#define BN 128
#define BKK 32
#define LDA_S 40
#define LDB_S 136
constexpr int STG_A_BYTES = BM * LDA_S * 2;
constexpr int STG_B_BYTES = BKK * LDB_S * 2;
constexpr int STG_BYTES = STG_A_BYTES + STG_B_BYTES;
constexpr int GEMM_SMEM = 4 * STG_BYTES;             // 75776

__device__ __forceinline__ void cp16(uint32_t s, const void* g, int pbytes) {
    asm volatile("cp.async.cg.shared.global [%0], [%1], 16, %2;\n" ::"r"(s), "l"(g), "r"(pbytes));
}
__device__ __forceinline__ void ldsm_x4(uint32_t* r, uint32_t addr) {
    asm volatile("ldmatrix.sync.aligned.m8n8.x4.shared.b16 {%0,%1,%2,%3}, [%4];"
                 : "=r"(r[0]), "=r"(r[1]), "=r"(r[2]), "=r"(r[3]) : "r"(addr));
}
__device__ __forceinline__ void ldsm_x4_t(uint32_t* r, uint32_t addr) {
    asm volatile("ldmatrix.sync.aligned.m8n8.x4.trans.shared.b16 {%0,%1,%2,%3}, [%4];"
                 : "=r"(r[0]), "=r"(r[1]), "=r"(r[2]), "=r"(r[3]) : "r"(addr));
}
__device__ __forceinline__ void mma16816(float* c, const uint32_t* a, uint32_t b0, uint32_t b1) {
    asm volatile(
        "mma.sync.aligned.m16n8k16.row.col.f32.f16.f16.f32 "
        "{%0,%1,%2,%3}, {%4,%5,%6,%7}, {%8,%9}, {%0,%1,%2,%3};"
        : "+f"(c[0]), "+f"(c[1]), "+f"(c[2]), "+f"(c[3])
        : "r"(a[0]), "r"(a[1]), "r"(a[2]), "r"(a[3]), "r"(b0), "r"(b1));
}

// ldb/ldc: row strides (elements) of B and C, allowing N-sliced sub-GEMMs.
template <typename OutT, bool FUSE>
__global__ void __launch_bounds__(256, 2) gemm_kernel(
    const __half* __restrict__ A, const __half* __restrict__ B, OutT* __restrict__ C,
    const float* __restrict__ bias, int M, int N, int K, int ldb, int ldc) {
    extern __shared__ __align__(128) char dsm[];
    const int tid = threadIdx.x, lane = tid & 31, wid = tid >> 5;
    const int rowBase = blockIdx.y * BM, colBase = blockIdx.x * BN;
    const int wm = (wid >> 1) * 32, wn = (wid & 1) * 64;

    const uint32_t sbase = (uint32_t)__cvta_generic_to_shared(dsm);

    auto load_tiles = [&](int stage, int k0) {
        uint32_t sAa = sbase + stage * STG_BYTES;
        uint32_t sBa = sAa + STG_A_BYTES;
        #pragma unroll
        for (int i = 0; i < 2; i++) {
            int c = tid + i * 256;
            int r = c >> 2, cw = c & 3;
            int gr = rowBase + r;
            const __half* gp = A + (size_t)min(gr, M - 1) * K + k0 + cw * 8;
            cp16(sAa + (r * LDA_S + cw * 8) * 2, gp, (gr < M) ? 16 : 0);
        }
        #pragma unroll
        for (int i = 0; i < 2; i++) {
            int c = tid + i * 256;
            int r = c >> 4, cw = c & 15;
            const __half* gp = B + (size_t)(k0 + r) * ldb + colBase + cw * 8;
            cp16(sBa + (r * LDB_S + cw * 8) * 2, gp, 16);
        }
        asm volatile("cp.async.commit_group;\n");
    };

    float acc[2][8][4];
    #pragma unroll
    for (int a = 0; a < 2; a++)
        #pragma unroll
        for (int b = 0; b < 8; b++)
            #pragma unroll
            for (int c = 0; c < 4; c++) acc[a][b][c] = 0.f;

    const int KT = K / BKK;
    load_tiles(0, 0);
    if (KT > 1) load_tiles(1, BKK);
    if (KT > 2) load_tiles(2, 2 * BKK);
    const int aRowL = lane & 15, aColL = (lane >> 4) << 3;
    const int bRowL = (lane & 7) + ((lane >> 3) & 1) * 8, bColL = (lane >> 4) << 3;

    int st = 0;
    for (int kt = 0; kt < KT; ++kt) {
        int pend = KT - 1 - kt; if (pend > 2) pend = 2;
        if (pend == 2)      asm volatile("cp.async.wait_group 2;\n");
        else if (pend == 1) asm volatile("cp.async.wait_group 1;\n");
        else                asm volatile("cp.async.wait_group 0;\n");
        __syncthreads();
        if (kt + 3 < KT) load_tiles((st + 3) & 3, (kt + 3) * BKK);
        uint32_t aB = sbase + st * STG_BYTES, bB = aB + STG_A_BYTES;
        #pragma unroll
        for (int ks = 0; ks < 2; ++ks) {
            int k0 = ks * 16;
            uint32_t af[2][4], bf[4][4];
            #pragma unroll
            for (int mt = 0; mt < 2; ++mt)
                ldsm_x4(af[mt], aB + ((wm + mt * 16 + aRowL) * LDA_S + k0 + aColL) * 2);
            #pragma unroll
            for (int np = 0; np < 4; ++np)
                ldsm_x4_t(bf[np], bB + ((k0 + bRowL) * LDB_S + wn + np * 16 + bColL) * 2);
            #pragma unroll
            for (int mt = 0; mt < 2; ++mt)
                #pragma unroll
                for (int nt = 0; nt < 8; ++nt)
                    mma16816(acc[mt][nt], af[mt], bf[nt >> 1][(nt & 1) * 2],
                             bf[nt >> 1][(nt & 1) * 2 + 1]);
        }
        st = (st + 1) & 3;
    }

    const int g = lane >> 2, cp2 = (lane & 3) * 2;
    #pragma unroll
    for (int mt = 0; mt < 2; ++mt) {
        #pragma unroll
        for (int nt = 0; nt < 8; ++nt) {
            int col = colBase + wn + nt * 8 + cp2;
            #pragma unroll
            for (int h = 0; h < 2; ++h) {
                int r = rowBase + wm + mt * 16 + g + h * 8;
                if (r < M) {
                    float v0 = acc[mt][nt][h * 2 + 0];
                    float v1 = acc[mt][nt][h * 2 + 1];
                    if (FUSE) {
                        v0 += __ldg(&bias[col]);
                        v1 += __ldg(&bias[col + 1]);
                        v0 = v0 >= 0.f ? v0 : 0.2f * v0;
                        v1 = v1 >= 0.f ? v1 : 0.2f * v1;
                    }
                    if constexpr (sizeof(OutT) == 2) {
                        *reinterpret_cast<__half2*>(&C[(size_t)r * ldc + col]) =
                            __floats2half2_rn(v0, v1);
                    } else {
                        *reinterpret_cast<float2*>(&C[(size_t)r * ldc + col]) =
                            make_float2(v0, v1);
                    }
                }
            }
        }
    }
}

// ---------------- launch ----------------
extern "C" void kernel_launch(void* const* d_in, const int* in_sizes, int n_in,
                              void* d_out, int out_size) {
    const float* x    = (const float*)d_in[0];
    const int*   erow = (const int*)d_in[1];
    const int*   ecol = (const int*)d_in[2];
    const float* eval = (const float*)d_in[3];
    const float* W0 = (const float*)d_in[4];
    const float* b0 = (const float*)d_in[5];
    const float* W1 = (const float*)d_in[6];
    const float* b1 = (const float*)d_in[7];
    const float* W2 = (const float*)d_in[8];
    const float* b2 = (const float*)d_in[9];
    const int E = in_sizes[1];

    int *cnt, *rowptr, *cursor;
    int2* epair;
    __half *xh, *t1, *h1, *s2, *h2, *s3, *W0h, *W1h, *W2h;
    cudaGetSymbolAddress((void**)&cnt, g_cnt);
    cudaGetSymbolAddress((void**)&rowptr, g_rowptr);
    cudaGetSymbolAddress((void**)&cursor, g_cursor);
    cudaGetSymbolAddress((void**)&epair, g_epair);
    cudaGetSymbolAddress((void**)&xh, g_xh);
    cudaGetSymbolAddress((void**)&t1, g_t1);
    cudaGetSymbolAddress((void**)&h1, g_h1);
    cudaGetSymbolAddress((void**)&s2, g_s2);
    cudaGetSymbolAddress((void**)&h2, g_h2);
    cudaGetSymbolAddress((void**)&s3, g_s3);
    cudaGetSymbolAddress((void**)&W0h, g_W0h);
    cudaGetSymbolAddress((void**)&W1h, g_W1h);
    cudaGetSymbolAddress((void**)&W2h, g_W2h);

    cudaFuncSetAttribute(gemm_kernel<__half, true>,
                         cudaFuncAttributeMaxDynamicSharedMemorySize, GEMM_SMEM);
    cudaFuncSetAttribute(gemm_kernel<__half, false>,
                         cudaFuncAttributeMaxDynamicSharedMemorySize, GEMM_SMEM);

    // side stream + events (host objects only; never destroyed so graph capture stays valid)
    cudaStream_t s1;
    cudaStreamCreate(&s1);
    cudaEvent_t evF, ev1, ev2, ev3, ev4;
    cudaEventCreateWithFlags(&evF, cudaEventDisableTiming);
    cudaEventCreateWithFlags(&ev1, cudaEventDisableTiming);
    cudaEventCreateWithFlags(&ev2, cudaEventDisableTiming);
    cudaEventCreateWithFlags(&ev3, cudaEventDisableTiming);
    cudaEventCreateWithFlags(&ev4, cudaEventDisableTiming);

    // ---- fork s1 early: W1/W2 conversion overlaps the CSR build ----
    cudaEventRecord(evF, 0);
    cudaStreamWaitEvent(s1, evF, 0);
    f2h2_kernel<<<512, 256, 0, s1>>>(W1, W1h, D1 * D2, W2, W2h, D2 * D3);

    // ---- main stream: CSR build + normalize (+W0 f2h) ----
    normh_count_kernel<<<N_NODES, 128>>>(x, xh, erow, cnt, E, W0, W0h, D0 * D1);
    scan_kernel<<<1, 1024>>>(cnt, rowptr, cursor);
    scatter_kernel<<<(E + 255) / 256, 256>>>(erow, ecol, eval, cursor, epair, cnt, E);

    // ---- layer 1: M-split; spmm1_B overlaps gemm1_A ----
    spmm_h_kernel<D0, false, false, __half>
        <<<M_HALF, D0 / 8>>>(rowptr, epair, xh, nullptr, t1, 0, 0);
    cudaEventRecord(ev1, 0);
    cudaStreamWaitEvent(s1, ev1, 0);
    gemm_kernel<__half, true>
        <<<dim3(D1 / BN, (M_HALF + BM - 1) / BM), 256, GEMM_SMEM, s1>>>(
            t1, W0h, h1, b0, M_HALF, D1, D0, D1, D1);
    cudaEventRecord(ev2, s1);
    spmm_h_kernel<D0, false, false, __half>
        <<<N_NODES - M_HALF, D0 / 8>>>(rowptr, epair, xh, nullptr, t1, M_HALF, 0);
    gemm_kernel<__half, true>
        <<<dim3(D1 / BN, (N_NODES - M_HALF + BM - 1) / BM), 256, GEMM_SMEM>>>(
            t1 + (size_t)M_HALF * D0, W0h, h1 + (size_t)M_HALF * D1, b0,
            N_NODES - M_HALF, D1, D0, D1, D1);
    cudaStreamWaitEvent(0, ev2, 0);          // join: h1 complete

    // ---- layer 2: N-split gemm2; spmm2_colA overlaps gemm2_NB ----
    gemm_kernel<__half, false>
        <<<dim3((D2 / 2) / BN, (N_NODES + BM - 1) / BM), 256, GEMM_SMEM>>>(
            h1, W1h, s2, nullptr, N_NODES, D2 / 2, D1, D2, D2);
    cudaEventRecord(ev3, 0);
    cudaStreamWaitEvent(s1, ev3, 0);
    spmm_h_kernel<D2, true, true, __half>
        <<<N_NODES, 64, 0, s1>>>(rowptr, epair, s2, b1, h2, 0, 0);
    cudaEventRecord(ev4, s1);
    gemm_kernel<__half, false>
        <<<dim3((D2 / 2) / BN, (N_NODES + BM - 1) / BM), 256, GEMM_SMEM>>>(
            h1, W1h + D2 / 2, s2 + D2 / 2, nullptr, N_NODES, D2 / 2, D1, D2, D2);
    spmm_h_kernel<D2, true, true, __half>
        <<<N_NODES, 64>>>(rowptr, epair, s2, b1 + D2 / 2, h2, 0, (D2 / 2) / 8);
    cudaStreamWaitEvent(0, ev4, 0);          // join: h2 complete

    // ---- layer 3 (serial: best-known configuration) ----
    gemm_kernel<__half, false>
        <<<dim3(D3 / BN, (N_NODES + BM - 1) / BM), 256, GEMM_SMEM>>>(
            h2, W2h, s3, nullptr, N_NODES, D3, D2, D3, D3);
    spmm_h_kernel<D3, true, false, float>
        <<<N_NODES, D3 / 8>>>(rowptr, epair, s3, b2, (float*)d_out, 0, 0);
}